// round 6
// baseline (speedup 1.0000x reference)
#include <cuda_runtime.h>
#include <math.h>

// ---------------------------------------------------------------------------
// PhysicsEmbedding: algebraic collapse of the whole pipeline.
//   B=32, S=4096, D=1024, H=256
// out[b,s,:] = A1·p[b,s] + A2·vel[b,s] + A3·acc[b,s] + g[b,:]
// where A1=Wo[:,0:256]@Wp, A2=Wo[:,256:512]@Wv, A3=Wo[:,512:768]@Wa,
//       A4=Wo[:,768:1024]@Wf, c = bo + Wo1@bp + Wo2@bv + Wo3@ba + Wo4@bf,
//       g[b,:] = A4 @ freq[b] + c   (freq = |16-bin DFT| per channel)
// ---------------------------------------------------------------------------

#define B_ 32
#define S_ 4096
#define D_ 1024
#define H_ 256
#define SCHUNK 16

__device__ float g_freq[B_ * 32];        // |DFT bins|, [b][j], j = c*16+k
__device__ float g_a1x[D_], g_a1y[D_];
__device__ float g_a2x[D_], g_a2y[D_];
__device__ float g_a3x[D_], g_a3y[D_];
__device__ float g_A4[D_ * 32];
__device__ float g_cbias[D_];
__device__ float g_g[B_ * D_];           // per-batch constant vector

// ---------------------------------------------------------------------------
// 1) 16-bin DFT magnitude via shared twiddle table.
//    One block per batch, 1024 threads. Warp w = bin j (c=w>>4, k=w&15).
// ---------------------------------------------------------------------------
__global__ void __launch_bounds__(1024) dft_kernel(const float* __restrict__ pattern) {
    int b = blockIdx.x;
    int tid = threadIdx.x;

    __shared__ float2 tw[S_];            // 32 KB
#pragma unroll
    for (int u = 0; u < 4; u++) {
        int t = tid * 4 + u;
        float sn, cs;
        // angle in pi-units: -2*t/4096 = -t/2048 (exact fp32)
        sincospif((float)t * (-1.0f / 2048.0f), &sn, &cs);
        tw[t] = make_float2(cs, sn);
    }
    __syncthreads();

    int w = tid >> 5;                    // warp = j index 0..31
    int lane = tid & 31;
    int c = w >> 4;
    int k = w & 15;

    const float* pp = pattern + (size_t)b * S_ * 2 + c;
    float re = 0.f, im = 0.f;
    for (int t = lane; t < S_; t += 32) {
        float x = pp[t * 2];
        float2 wv = tw[(k * t) & (S_ - 1)];
        re += x * wv.x;
        im += x * wv.y;
    }
#pragma unroll
    for (int off = 16; off > 0; off >>= 1) {
        re += __shfl_down_sync(0xffffffffu, re, off);
        im += __shfl_down_sync(0xffffffffu, im, off);
    }
    if (lane == 0)
        g_freq[b * 32 + w] = sqrtf(re * re + im * im);
}

// ---------------------------------------------------------------------------
// 2) Fold the small matrices through Wo. One block (64 thr) per output row d.
//    Warp 0: A4 row with lane=j (coalesced Wf loads, broadcast wo loads).
//    Warp 1: the six 2-wide coefficients + fused bias (strided h, shuffles).
// ---------------------------------------------------------------------------
__global__ void __launch_bounds__(64) coeff_kernel(
        const float* __restrict__ Wp, const float* __restrict__ bp,
        const float* __restrict__ Wv, const float* __restrict__ bv,
        const float* __restrict__ Wa, const float* __restrict__ ba,
        const float* __restrict__ Wf, const float* __restrict__ bfr,
        const float* __restrict__ Wo, const float* __restrict__ bo) {
    int d = blockIdx.x;
    int warp = threadIdx.x >> 5;
    int lane = threadIdx.x & 31;
    const float* wo = Wo + (size_t)d * D_;

    if (warp == 0) {
        // A4[d][lane] = sum_h Wo[d][768+h] * Wf[h][lane]
        float a4 = 0.f;
#pragma unroll 8
        for (int h = 0; h < H_; h++) {
            float w3 = wo[768 + h];                 // uniform broadcast
            a4 += w3 * Wf[h * 32 + lane];           // coalesced: 1 line/req
        }
        g_A4[d * 32 + lane] = a4;
    } else {
        float a1x = 0, a1y = 0, a2x = 0, a2y = 0, a3x = 0, a3y = 0, bias = 0;
#pragma unroll
        for (int h = lane; h < H_; h += 32) {
            float w0 = wo[h];
            float w1 = wo[256 + h];
            float w2 = wo[512 + h];
            float w3 = wo[768 + h];
            a1x += w0 * Wp[h * 2 + 0];  a1y += w0 * Wp[h * 2 + 1];
            a2x += w1 * Wv[h * 2 + 0];  a2y += w1 * Wv[h * 2 + 1];
            a3x += w2 * Wa[h * 2 + 0];  a3y += w2 * Wa[h * 2 + 1];
            bias += w0 * bp[h] + w1 * bv[h] + w2 * ba[h] + w3 * bfr[h];
        }
#pragma unroll
        for (int off = 16; off > 0; off >>= 1) {
            a1x += __shfl_down_sync(0xffffffffu, a1x, off);
            a1y += __shfl_down_sync(0xffffffffu, a1y, off);
            a2x += __shfl_down_sync(0xffffffffu, a2x, off);
            a2y += __shfl_down_sync(0xffffffffu, a2y, off);
            a3x += __shfl_down_sync(0xffffffffu, a3x, off);
            a3y += __shfl_down_sync(0xffffffffu, a3y, off);
            bias += __shfl_down_sync(0xffffffffu, bias, off);
        }
        if (lane == 0) {
            g_a1x[d] = a1x; g_a1y[d] = a1y;
            g_a2x[d] = a2x; g_a2y[d] = a2y;
            g_a3x[d] = a3x; g_a3y[d] = a3y;
            g_cbias[d] = bias + bo[d];
        }
    }
}

// ---------------------------------------------------------------------------
// 3) Per-batch constant vector g[b,d] = c[d] + A4[d,:]·freq[b,:]
// ---------------------------------------------------------------------------
__global__ void gtab_kernel() {
    int b = blockIdx.x;
    int tid = threadIdx.x;           // 256 threads, 4 d's each
    __shared__ float fr[32];
    if (tid < 32) fr[tid] = g_freq[b * 32 + tid];
    __syncthreads();
#pragma unroll
    for (int i = 0; i < 4; i++) {
        int d = tid * 4 + i;
        float acc = g_cbias[d];
        const float* a4 = g_A4 + d * 32;
#pragma unroll
        for (int j = 0; j < 32; j++) acc += a4[j] * fr[j];
        g_g[b * D_ + d] = acc;
    }
}

// ---------------------------------------------------------------------------
// 4) Main write kernel: HBM-write bound (537 MB of output).
//    One block covers D=1024 (256 thr x float4) for SCHUNK timesteps.
// ---------------------------------------------------------------------------
__global__ void __launch_bounds__(256) main_kernel(const float* __restrict__ pattern,
                                                   float* __restrict__ out) {
    int b = blockIdx.y;
    int s0 = blockIdx.x * SCHUNK;
    int tid = threadIdx.x;
    int d = tid * 4;

    __shared__ float sp[(SCHUNK + 2) * 2];   // pattern[b, s0-2 .. s0+SCHUNK-1]
    if (tid < (SCHUNK + 2) * 2) {
        int s = s0 - 2 + (tid >> 1);
        int c = tid & 1;
        sp[tid] = (s >= 0) ? pattern[((size_t)b * S_ + s) * 2 + c] : 0.0f;
    }

    float4 k1x = *(const float4*)(g_a1x + d);
    float4 k1y = *(const float4*)(g_a1y + d);
    float4 k2x = *(const float4*)(g_a2x + d);
    float4 k2y = *(const float4*)(g_a2y + d);
    float4 k3x = *(const float4*)(g_a3x + d);
    float4 k3y = *(const float4*)(g_a3y + d);
    float4 gg  = *(const float4*)(g_g + b * D_ + d);
    __syncthreads();

    float* op = out + ((size_t)b * S_ + s0) * D_ + d;

#pragma unroll
    for (int i = 0; i < SCHUNK; i++) {
        int s = s0 + i;
        float px = sp[(i + 2) * 2 + 0], py = sp[(i + 2) * 2 + 1];
        float mx = sp[(i + 1) * 2 + 0], my = sp[(i + 1) * 2 + 1];
        float nx = sp[(i + 0) * 2 + 0], ny = sp[(i + 0) * 2 + 1];

        float vx, vy, ax_, ay_;
        if (s == 0) {
            vx = 0.f; vy = 0.f; ax_ = 0.f; ay_ = 0.f;
        } else if (s == 1) {
            vx = px - mx; vy = py - my; ax_ = vx; ay_ = vy;
        } else {
            vx = px - mx; vy = py - my;
            ax_ = px - 2.f * mx + nx; ay_ = py - 2.f * my + ny;
        }

        float4 o;
        o.x = gg.x + k1x.x * px + k1y.x * py + k2x.x * vx + k2y.x * vy + k3x.x * ax_ + k3y.x * ay_;
        o.y = gg.y + k1x.y * px + k1y.y * py + k2x.y * vx + k2y.y * vy + k3x.y * ax_ + k3y.y * ay_;
        o.z = gg.z + k1x.z * px + k1y.z * py + k2x.z * vx + k2y.z * vy + k3x.z * ax_ + k3y.z * ay_;
        o.w = gg.w + k1x.w * px + k1y.w * py + k2x.w * vx + k2y.w * vy + k3x.w * ax_ + k3y.w * ay_;

        *(float4*)(op + (size_t)i * D_) = o;
    }
}

// ---------------------------------------------------------------------------
extern "C" void kernel_launch(void* const* d_in, const int* in_sizes, int n_in,
                              void* d_out, int out_size) {
    const float* pattern = (const float*)d_in[0];
    const float* Wp  = (const float*)d_in[1];
    const float* bp  = (const float*)d_in[2];
    const float* Wv  = (const float*)d_in[3];
    const float* bv  = (const float*)d_in[4];
    const float* Wa  = (const float*)d_in[5];
    const float* ba  = (const float*)d_in[6];
    const float* Wf  = (const float*)d_in[7];
    const float* bfr = (const float*)d_in[8];
    const float* Wo  = (const float*)d_in[9];
    const float* bo  = (const float*)d_in[10];
    float* out = (float*)d_out;

    dft_kernel<<<B_, 1024>>>(pattern);
    coeff_kernel<<<D_, 64>>>(Wp, bp, Wv, bv, Wa, ba, Wf, bfr, Wo, bo);
    gtab_kernel<<<B_, 256>>>();
    main_kernel<<<dim3(S_ / SCHUNK, B_), 256>>>(pattern, out);
}

// round 8
// speedup vs baseline: 1.4516x; 1.4516x over previous
#include <cuda_runtime.h>
#include <math.h>

// ---------------------------------------------------------------------------
// PhysicsEmbedding: algebraic collapse of the whole pipeline.
//   B=32, S=4096, D=1024, H=256
// out[b,s,:] = A1·p[b,s] + A2·vel[b,s] + A3·acc[b,s] + g[b,:]
// g[b,:] = A4 @ freq[b] + c,  freq = |16-bin DFT| per channel
// ---------------------------------------------------------------------------

#define B_ 32
#define S_ 4096
#define D_ 1024
#define H_ 256
#define SCHUNK 16
#define DCHUNK 4          // S-chunks for DFT partials

__device__ float2 g_dpart[B_ * 32 * DCHUNK];   // DFT partial (re,im) [b][j][chunk]
__device__ float g_a1x[D_], g_a1y[D_];
__device__ float g_a2x[D_], g_a2y[D_];
__device__ float g_a3x[D_], g_a3y[D_];
__device__ float g_A4T[32 * D_];               // transposed: [j][d]
__device__ float g_cbias[D_];
__device__ float g_g[B_ * D_];                 // per-batch constant vector

// ---------------------------------------------------------------------------
// 1) 16-bin DFT partials via per-lane complex recurrence (no shared memory).
//    grid (DCHUNK, B_), 1024 threads; warp w = bin j (c=w>>4, k=w&15).
//    Lane handles t = chunk*1024 + lane + 32*i, i=0..31.
// ---------------------------------------------------------------------------
__global__ void __launch_bounds__(1024) dft_kernel(const float* __restrict__ pattern) {
    int chunk = blockIdx.x;
    int b = blockIdx.y;
    int w = threadIdx.x >> 5;            // bin j = c*16 + k
    int lane = threadIdx.x & 31;
    int c = w >> 4;
    int k = w & 15;

    int t0 = chunk * (S_ / DCHUNK) + lane;
    // W[n] = e^{-2*pi*i*n/4096}; angles in pi-units (exact fp32 after &4095)
    float a0 = (float)((k * t0) & (S_ - 1)) * (-1.0f / 2048.0f);
    float as = (float)((k * 32) & (S_ - 1)) * (-1.0f / 2048.0f);
    float wr, wi, sr, si;
    sincospif(a0, &wi, &wr);
    sincospif(as, &si, &sr);

    const float* pp = pattern + ((size_t)b * S_ + chunk * (S_ / DCHUNK)) * 2 + c;
    float re = 0.f, im = 0.f;
#pragma unroll
    for (int i = 0; i < 32; i++) {
        float x = pp[(lane + i * 32) * 2];
        re += x * wr;
        im += x * wi;
        float nr = wr * sr - wi * si;    // w *= step
        float ni = wr * si + wi * sr;
        wr = nr; wi = ni;
    }
#pragma unroll
    for (int off = 16; off > 0; off >>= 1) {
        re += __shfl_down_sync(0xffffffffu, re, off);
        im += __shfl_down_sync(0xffffffffu, im, off);
    }
    if (lane == 0)
        g_dpart[(b * 32 + w) * DCHUNK + chunk] = make_float2(re, im);
}

// ---------------------------------------------------------------------------
// 2) Fold the small matrices through Wo. One block (64 thr) per output row d.
//    Warp 0: A4 row, lane=j (coalesced Wf, broadcast wo), written TRANSPOSED.
//    Warp 1: the six 2-wide coefficients + fused bias.
// ---------------------------------------------------------------------------
__global__ void __launch_bounds__(64) coeff_kernel(
        const float* __restrict__ Wp, const float* __restrict__ bp,
        const float* __restrict__ Wv, const float* __restrict__ bv,
        const float* __restrict__ Wa, const float* __restrict__ ba,
        const float* __restrict__ Wf, const float* __restrict__ bfr,
        const float* __restrict__ Wo, const float* __restrict__ bo) {
    int d = blockIdx.x;
    int warp = threadIdx.x >> 5;
    int lane = threadIdx.x & 31;
    const float* wo = Wo + (size_t)d * D_;

    if (warp == 0) {
        float a4 = 0.f;
#pragma unroll 8
        for (int h = 0; h < H_; h++) {
            float w3 = wo[768 + h];                 // uniform broadcast
            a4 += w3 * Wf[h * 32 + lane];           // coalesced
        }
        g_A4T[lane * D_ + d] = a4;                  // transposed store
    } else {
        float a1x = 0, a1y = 0, a2x = 0, a2y = 0, a3x = 0, a3y = 0, bias = 0;
#pragma unroll
        for (int h = lane; h < H_; h += 32) {
            float w0 = wo[h];
            float w1 = wo[256 + h];
            float w2 = wo[512 + h];
            float w3 = wo[768 + h];
            a1x += w0 * Wp[h * 2 + 0];  a1y += w0 * Wp[h * 2 + 1];
            a2x += w1 * Wv[h * 2 + 0];  a2y += w1 * Wv[h * 2 + 1];
            a3x += w2 * Wa[h * 2 + 0];  a3y += w2 * Wa[h * 2 + 1];
            bias += w0 * bp[h] + w1 * bv[h] + w2 * ba[h] + w3 * bfr[h];
        }
#pragma unroll
        for (int off = 16; off > 0; off >>= 1) {
            a1x += __shfl_down_sync(0xffffffffu, a1x, off);
            a1y += __shfl_down_sync(0xffffffffu, a1y, off);
            a2x += __shfl_down_sync(0xffffffffu, a2x, off);
            a2y += __shfl_down_sync(0xffffffffu, a2y, off);
            a3x += __shfl_down_sync(0xffffffffu, a3x, off);
            a3y += __shfl_down_sync(0xffffffffu, a3y, off);
            bias += __shfl_down_sync(0xffffffffu, bias, off);
        }
        if (lane == 0) {
            g_a1x[d] = a1x; g_a1y[d] = a1y;
            g_a2x[d] = a2x; g_a2y[d] = a2y;
            g_a3x[d] = a3x; g_a3y[d] = a3y;
            g_cbias[d] = bias + bo[d];
        }
    }
}

// ---------------------------------------------------------------------------
// 3) g[b,d] = cbias[d] + sum_j freq[b,j] * A4T[j][d].
//    One block per batch, 1024 threads (thread = d, coalesced A4T reads).
//    First 32 threads finish the DFT: freq[j] = |sum_chunk partial|.
// ---------------------------------------------------------------------------
__global__ void __launch_bounds__(1024) gtab_kernel() {
    int b = blockIdx.x;
    int tid = threadIdx.x;
    __shared__ float fr[32];
    if (tid < 32) {
        float re = 0.f, im = 0.f;
#pragma unroll
        for (int ch = 0; ch < DCHUNK; ch++) {
            float2 p = g_dpart[(b * 32 + tid) * DCHUNK + ch];
            re += p.x; im += p.y;
        }
        fr[tid] = sqrtf(re * re + im * im);
    }
    __syncthreads();

    float acc = g_cbias[tid];
#pragma unroll
    for (int j = 0; j < 32; j++)
        acc += fr[j] * g_A4T[j * D_ + tid];         // coalesced, fr broadcast
    g_g[b * D_ + tid] = acc;
}

// ---------------------------------------------------------------------------
// 4) Main write kernel: HBM-write bound (537 MB of output), at the roofline.
// ---------------------------------------------------------------------------
__global__ void __launch_bounds__(256) main_kernel(const float* __restrict__ pattern,
                                                   float* __restrict__ out) {
    int b = blockIdx.y;
    int s0 = blockIdx.x * SCHUNK;
    int tid = threadIdx.x;
    int d = tid * 4;

    __shared__ float sp[(SCHUNK + 2) * 2];   // pattern[b, s0-2 .. s0+SCHUNK-1]
    if (tid < (SCHUNK + 2) * 2) {
        int s = s0 - 2 + (tid >> 1);
        int c = tid & 1;
        sp[tid] = (s >= 0) ? pattern[((size_t)b * S_ + s) * 2 + c] : 0.0f;
    }

    float4 k1x = *(const float4*)(g_a1x + d);
    float4 k1y = *(const float4*)(g_a1y + d);
    float4 k2x = *(const float4*)(g_a2x + d);
    float4 k2y = *(const float4*)(g_a2y + d);
    float4 k3x = *(const float4*)(g_a3x + d);
    float4 k3y = *(const float4*)(g_a3y + d);
    float4 gg  = *(const float4*)(g_g + b * D_ + d);
    __syncthreads();

    float* op = out + ((size_t)b * S_ + s0) * D_ + d;

#pragma unroll
    for (int i = 0; i < SCHUNK; i++) {
        int s = s0 + i;
        float px = sp[(i + 2) * 2 + 0], py = sp[(i + 2) * 2 + 1];
        float mx = sp[(i + 1) * 2 + 0], my = sp[(i + 1) * 2 + 1];
        float nx = sp[(i + 0) * 2 + 0], ny = sp[(i + 0) * 2 + 1];

        float vx, vy, ax_, ay_;
        if (s == 0) {
            vx = 0.f; vy = 0.f; ax_ = 0.f; ay_ = 0.f;
        } else if (s == 1) {
            vx = px - mx; vy = py - my; ax_ = vx; ay_ = vy;
        } else {
            vx = px - mx; vy = py - my;
            ax_ = px - 2.f * mx + nx; ay_ = py - 2.f * my + ny;
        }

        float4 o;
        o.x = gg.x + k1x.x * px + k1y.x * py + k2x.x * vx + k2y.x * vy + k3x.x * ax_ + k3y.x * ay_;
        o.y = gg.y + k1x.y * px + k1y.y * py + k2x.y * vx + k2y.y * vy + k3x.y * ax_ + k3y.y * ay_;
        o.z = gg.z + k1x.z * px + k1y.z * py + k2x.z * vx + k2y.z * vy + k3x.z * ax_ + k3y.z * ay_;
        o.w = gg.w + k1x.w * px + k1y.w * py + k2x.w * vx + k2y.w * vy + k3x.w * ax_ + k3y.w * ay_;

        *(float4*)(op + (size_t)i * D_) = o;
    }
}

// ---------------------------------------------------------------------------
extern "C" void kernel_launch(void* const* d_in, const int* in_sizes, int n_in,
                              void* d_out, int out_size) {
    const float* pattern = (const float*)d_in[0];
    const float* Wp  = (const float*)d_in[1];
    const float* bp  = (const float*)d_in[2];
    const float* Wv  = (const float*)d_in[3];
    const float* bv  = (const float*)d_in[4];
    const float* Wa  = (const float*)d_in[5];
    const float* ba  = (const float*)d_in[6];
    const float* Wf  = (const float*)d_in[7];
    const float* bfr = (const float*)d_in[8];
    const float* Wo  = (const float*)d_in[9];
    const float* bo  = (const float*)d_in[10];
    float* out = (float*)d_out;

    dft_kernel<<<dim3(DCHUNK, B_), 1024>>>(pattern);
    coeff_kernel<<<D_, 64>>>(Wp, bp, Wv, bv, Wa, ba, Wf, bfr, Wo, bo);
    gtab_kernel<<<B_, 1024>>>();
    main_kernel<<<dim3(S_ / SCHUNK, B_), 256>>>(pattern, out);
}

// round 10
// speedup vs baseline: 1.4549x; 1.0023x over previous
#include <cuda_runtime.h>
#include <math.h>

// ---------------------------------------------------------------------------
// PhysicsEmbedding: algebraic collapse of the whole pipeline.
//   B=32, S=4096, D=1024, H=256
// out[b,s,:] = A1·p[b,s] + A2·vel[b,s] + A3·acc[b,s] + g[b,:]
// g[b,:] = A4 @ freq[b] + c,  freq = |16-bin DFT| per channel
// ---------------------------------------------------------------------------

#define B_ 32
#define S_ 4096
#define D_ 1024
#define H_ 256
#define SCHUNK 16
#define DCHUNK 4                    // S-chunks for DFT partials
#define NDFT (DCHUNK * B_)          // 128 dft blocks
#define NCOEFF (D_ / 16)            // 64 coeff blocks (16 d-rows each)

__device__ float2 g_dpart[B_ * 32 * DCHUNK];   // DFT partial (re,im) [b][j][chunk]
__device__ float g_a1x[D_], g_a1y[D_];
__device__ float g_a2x[D_], g_a2y[D_];
__device__ float g_a3x[D_], g_a3y[D_];
__device__ float g_A4T[32 * D_];               // transposed: [j][d]
__device__ float g_cbias[D_];
__device__ float g_g[B_ * D_];                 // per-batch constant vector

// ---------------------------------------------------------------------------
// 1) Fused precompute: blocks [0,128) do DFT partials, blocks [128,192) fold
//    the small matrices through Wo. Both independent; one wave on the chip.
// ---------------------------------------------------------------------------
__global__ void __launch_bounds__(1024) pre_kernel(
        const float* __restrict__ pattern,
        const float* __restrict__ Wp, const float* __restrict__ bp,
        const float* __restrict__ Wv, const float* __restrict__ bv,
        const float* __restrict__ Wa, const float* __restrict__ ba,
        const float* __restrict__ Wf, const float* __restrict__ bfr,
        const float* __restrict__ Wo, const float* __restrict__ bo) {
    int bx = blockIdx.x;
    int tid = threadIdx.x;
    int lane = tid & 31;

    if (bx < NDFT) {
        // ---- DFT partials via per-lane complex recurrence (no smem) ----
        int chunk = bx & (DCHUNK - 1);
        int b = bx >> 2;
        int w = tid >> 5;                // bin j = c*16 + k
        int c = w >> 4;
        int k = w & 15;

        int t0 = chunk * (S_ / DCHUNK) + lane;
        float a0 = (float)((k * t0) & (S_ - 1)) * (-1.0f / 2048.0f);
        float as = (float)((k * 32) & (S_ - 1)) * (-1.0f / 2048.0f);
        float wr, wi, sr, si;
        sincospif(a0, &wi, &wr);
        sincospif(as, &si, &sr);

        const float* pp = pattern + ((size_t)b * S_ + chunk * (S_ / DCHUNK)) * 2 + c;
        float re = 0.f, im = 0.f;
#pragma unroll
        for (int i = 0; i < 32; i++) {
            float x = pp[(lane + i * 32) * 2];
            re += x * wr;
            im += x * wi;
            float nr = wr * sr - wi * si;    // w *= step
            float ni = wr * si + wi * sr;
            wr = nr; wi = ni;
        }
#pragma unroll
        for (int off = 16; off > 0; off >>= 1) {
            re += __shfl_down_sync(0xffffffffu, re, off);
            im += __shfl_down_sync(0xffffffffu, im, off);
        }
        if (lane == 0)
            g_dpart[(b * 32 + w) * DCHUNK + chunk] = make_float2(re, im);
    } else {
        // ---- Coefficient folding: 16 d-rows per block, 64 thr per row ----
        int sub = tid >> 6;                          // 0..15
        int d = (bx - NDFT) * 16 + sub;
        int halfwarp = (tid >> 5) & 1;               // role: 0=A4, 1=small
        const float* wo = Wo + (size_t)d * D_;

        if (halfwarp == 0) {
            float a4 = 0.f;
#pragma unroll 8
            for (int h = 0; h < H_; h++) {
                float w3 = wo[768 + h];              // uniform broadcast
                a4 += w3 * Wf[h * 32 + lane];        // coalesced
            }
            g_A4T[lane * D_ + d] = a4;               // transposed store
        } else {
            float a1x = 0, a1y = 0, a2x = 0, a2y = 0, a3x = 0, a3y = 0, bias = 0;
#pragma unroll
            for (int h = lane; h < H_; h += 32) {
                float w0 = wo[h];
                float w1 = wo[256 + h];
                float w2 = wo[512 + h];
                float w3 = wo[768 + h];
                a1x += w0 * Wp[h * 2 + 0];  a1y += w0 * Wp[h * 2 + 1];
                a2x += w1 * Wv[h * 2 + 0];  a2y += w1 * Wv[h * 2 + 1];
                a3x += w2 * Wa[h * 2 + 0];  a3y += w2 * Wa[h * 2 + 1];
                bias += w0 * bp[h] + w1 * bv[h] + w2 * ba[h] + w3 * bfr[h];
            }
#pragma unroll
            for (int off = 16; off > 0; off >>= 1) {
                a1x += __shfl_down_sync(0xffffffffu, a1x, off);
                a1y += __shfl_down_sync(0xffffffffu, a1y, off);
                a2x += __shfl_down_sync(0xffffffffu, a2x, off);
                a2y += __shfl_down_sync(0xffffffffu, a2y, off);
                a3x += __shfl_down_sync(0xffffffffu, a3x, off);
                a3y += __shfl_down_sync(0xffffffffu, a3y, off);
                bias += __shfl_down_sync(0xffffffffu, bias, off);
            }
            if (lane == 0) {
                g_a1x[d] = a1x; g_a1y[d] = a1y;
                g_a2x[d] = a2x; g_a2y[d] = a2y;
                g_a3x[d] = a3x; g_a3y[d] = a3y;
                g_cbias[d] = bias + bo[d];
            }
        }
    }
}

// ---------------------------------------------------------------------------
// 2) g[b,d] = cbias[d] + sum_j freq[b,j] * A4T[j][d].
//    grid (B_, 4) x 256 thr; thread = d within 256-chunk (coalesced A4T).
// ---------------------------------------------------------------------------
__global__ void __launch_bounds__(256) gtab_kernel() {
    int b = blockIdx.x;
    int d0 = blockIdx.y * 256;
    int tid = threadIdx.x;
    __shared__ float fr[32];
    if (tid < 32) {
        float re = 0.f, im = 0.f;
#pragma unroll
        for (int ch = 0; ch < DCHUNK; ch++) {
            float2 p = g_dpart[(b * 32 + tid) * DCHUNK + ch];
            re += p.x; im += p.y;
        }
        fr[tid] = sqrtf(re * re + im * im);
    }
    __syncthreads();

    int d = d0 + tid;
    float acc = g_cbias[d];
#pragma unroll
    for (int j = 0; j < 32; j++)
        acc += fr[j] * g_A4T[j * D_ + d];           // coalesced, fr broadcast
    g_g[b * D_ + d] = acc;
}

// ---------------------------------------------------------------------------
// 3) Main write kernel: HBM-write bound (537 MB of output), at the roofline.
//    PDL: stage the pattern tile first (independent of precompute), then
//    grid-dependency-sync, then pull coefficients.
// ---------------------------------------------------------------------------
__global__ void __launch_bounds__(256) main_kernel(const float* __restrict__ pattern,
                                                   float* __restrict__ out) {
    int b = blockIdx.y;
    int s0 = blockIdx.x * SCHUNK;
    int tid = threadIdx.x;
    int d = tid * 4;

    __shared__ float sp[(SCHUNK + 2) * 2];   // pattern[b, s0-2 .. s0+SCHUNK-1]
    if (tid < (SCHUNK + 2) * 2) {
        int s = s0 - 2 + (tid >> 1);
        int c = tid & 1;
        sp[tid] = (s >= 0) ? pattern[((size_t)b * S_ + s) * 2 + c] : 0.0f;
    }
#if __CUDA_ARCH__ >= 900
    cudaGridDependencySynchronize();
#endif
    float4 k1x = *(const float4*)(g_a1x + d);
    float4 k1y = *(const float4*)(g_a1y + d);
    float4 k2x = *(const float4*)(g_a2x + d);
    float4 k2y = *(const float4*)(g_a2y + d);
    float4 k3x = *(const float4*)(g_a3x + d);
    float4 k3y = *(const float4*)(g_a3y + d);
    float4 gg  = *(const float4*)(g_g + b * D_ + d);
    __syncthreads();

    float* op = out + ((size_t)b * S_ + s0) * D_ + d;

#pragma unroll
    for (int i = 0; i < SCHUNK; i++) {
        int s = s0 + i;
        float px = sp[(i + 2) * 2 + 0], py = sp[(i + 2) * 2 + 1];
        float mx = sp[(i + 1) * 2 + 0], my = sp[(i + 1) * 2 + 1];
        float nx = sp[(i + 0) * 2 + 0], ny = sp[(i + 0) * 2 + 1];

        float vx, vy, ax_, ay_;
        if (s == 0) {
            vx = 0.f; vy = 0.f; ax_ = 0.f; ay_ = 0.f;
        } else if (s == 1) {
            vx = px - mx; vy = py - my; ax_ = vx; ay_ = vy;
        } else {
            vx = px - mx; vy = py - my;
            ax_ = px - 2.f * mx + nx; ay_ = py - 2.f * my + ny;
        }

        float4 o;
        o.x = gg.x + k1x.x * px + k1y.x * py + k2x.x * vx + k2y.x * vy + k3x.x * ax_ + k3y.x * ay_;
        o.y = gg.y + k1x.y * px + k1y.y * py + k2x.y * vx + k2y.y * vy + k3x.y * ax_ + k3y.y * ay_;
        o.z = gg.z + k1x.z * px + k1y.z * py + k2x.z * vx + k2y.z * vy + k3x.z * ax_ + k3y.z * ay_;
        o.w = gg.w + k1x.w * px + k1y.w * py + k2x.w * vx + k2y.w * vy + k3x.w * ax_ + k3y.w * ay_;

        *(float4*)(op + (size_t)i * D_) = o;
    }
}

// ---------------------------------------------------------------------------
extern "C" void kernel_launch(void* const* d_in, const int* in_sizes, int n_in,
                              void* d_out, int out_size) {
    const float* pattern = (const float*)d_in[0];
    const float* Wp  = (const float*)d_in[1];
    const float* bp  = (const float*)d_in[2];
    const float* Wv  = (const float*)d_in[3];
    const float* bv  = (const float*)d_in[4];
    const float* Wa  = (const float*)d_in[5];
    const float* ba  = (const float*)d_in[6];
    const float* Wf  = (const float*)d_in[7];
    const float* bfr = (const float*)d_in[8];
    const float* Wo  = (const float*)d_in[9];
    const float* bo  = (const float*)d_in[10];
    float* out = (float*)d_out;

    pre_kernel<<<NDFT + NCOEFF, 1024>>>(pattern, Wp, bp, Wv, bv, Wa, ba,
                                        Wf, bfr, Wo, bo);
    gtab_kernel<<<dim3(B_, 4), 256>>>();

    // PDL on the final (dominant) kernel: overlap its launch/prologue with
    // gtab; main_kernel pre-syncs before touching precomputed tables.
    cudaLaunchAttribute at[1];
    at[0].id = cudaLaunchAttributeProgrammaticStreamSerialization;
    at[0].val.programmaticStreamSerializationAllowed = 1;

    cudaLaunchConfig_t cfg = {};
    cfg.gridDim = dim3(S_ / SCHUNK, B_);
    cfg.blockDim = dim3(256);
    cfg.stream = 0;
    cfg.attrs = at;
    cfg.numAttrs = 1;
    if (cudaLaunchKernelEx(&cfg, main_kernel, pattern, out) != cudaSuccess) {
        main_kernel<<<dim3(S_ / SCHUNK, B_), 256>>>(pattern, out);
    }
}

// round 11
// speedup vs baseline: 1.4892x; 1.0236x over previous
#include <cuda_runtime.h>
#include <math.h>

// ---------------------------------------------------------------------------
// PhysicsEmbedding: algebraic collapse of the whole pipeline.
//   B=32, S=4096, D=1024, H=256
// out[b,s,:] = A1·p[b,s] + A2·vel[b,s] + A3·acc[b,s] + g[b,:]
// g[b,:] = A4 @ freq[b] + c,  freq = |16-bin DFT| per channel
// ---------------------------------------------------------------------------

#define B_ 32
#define S_ 4096
#define D_ 1024
#define H_ 256
#define SCHUNK 16
#define DCHUNK 2                    // S-chunks for DFT partials
#define NDFT (DCHUNK * B_)          // 64 dft blocks
#define NCOEFF (D_ / 16)            // 64 coeff blocks (16 d-rows each)
#define TPT (S_ / DCHUNK / 32)      // 64 timesteps per thread in DFT

__device__ float2 g_dpart[B_ * 32 * DCHUNK];   // DFT partial (re,im) [b][j][chunk]
__device__ float g_a1x[D_], g_a1y[D_];
__device__ float g_a2x[D_], g_a2y[D_];
__device__ float g_a3x[D_], g_a3y[D_];
__device__ float g_A4T[32 * D_];               // transposed: [j][d]
__device__ float g_cbias[D_];
__device__ float g_g[B_ * D_];                 // per-batch constant vector

// ---------------------------------------------------------------------------
// 1) Fused precompute, ONE wave (128 blocks <= 148 SMs):
//    blocks [0,64): DFT partials, explicit 8-wide load batching (MLP=8).
//    blocks [64,128): coefficient folding, 8 partial accumulators.
// ---------------------------------------------------------------------------
__global__ void __launch_bounds__(1024) pre_kernel(
        const float* __restrict__ pattern,
        const float* __restrict__ Wp, const float* __restrict__ bp,
        const float* __restrict__ Wv, const float* __restrict__ bv,
        const float* __restrict__ Wa, const float* __restrict__ ba,
        const float* __restrict__ Wf, const float* __restrict__ bfr,
        const float* __restrict__ Wo, const float* __restrict__ bo) {
    int bx = blockIdx.x;
    int tid = threadIdx.x;
    int lane = tid & 31;

    if (bx < NDFT) {
        // ---- DFT partials via per-lane complex recurrence ----
        int chunk = bx & (DCHUNK - 1);
        int b = bx / DCHUNK;
        int w = tid >> 5;                // bin j = c*16 + k
        int c = w >> 4;
        int k = w & 15;

        int t0 = chunk * (S_ / DCHUNK) + lane;
        float a0 = (float)((k * t0) & (S_ - 1)) * (-1.0f / 2048.0f);
        float as = (float)((k * 32) & (S_ - 1)) * (-1.0f / 2048.0f);
        float wr, wi, sr, si;
        sincospif(a0, &wi, &wr);
        sincospif(as, &si, &sr);

        const float* pp = pattern + ((size_t)b * S_ + chunk * (S_ / DCHUNK)) * 2 + c;
        float re = 0.f, im = 0.f;
#pragma unroll
        for (int batch = 0; batch < TPT / 8; batch++) {
            float x[8];
#pragma unroll
            for (int u = 0; u < 8; u++)              // 8 independent LDGs
                x[u] = pp[(lane + (batch * 8 + u) * 32) * 2];
#pragma unroll
            for (int u = 0; u < 8; u++) {
                re += x[u] * wr;
                im += x[u] * wi;
                float nr = wr * sr - wi * si;        // w *= step
                float ni = wr * si + wi * sr;
                wr = nr; wi = ni;
            }
        }
#pragma unroll
        for (int off = 16; off > 0; off >>= 1) {
            re += __shfl_down_sync(0xffffffffu, re, off);
            im += __shfl_down_sync(0xffffffffu, im, off);
        }
        if (lane == 0)
            g_dpart[(b * 32 + w) * DCHUNK + chunk] = make_float2(re, im);
    } else {
        // ---- Coefficient folding: 16 d-rows per block, 64 thr per row ----
        int sub = tid >> 6;                          // 0..15
        int d = (bx - NDFT) * 16 + sub;
        int halfwarp = (tid >> 5) & 1;               // role: 0=A4, 1=small
        const float* wo = Wo + (size_t)d * D_;

        if (halfwarp == 0) {
            float acc[8];
#pragma unroll
            for (int u = 0; u < 8; u++) acc[u] = 0.f;
#pragma unroll 4
            for (int h = 0; h < H_; h += 8) {
#pragma unroll
                for (int u = 0; u < 8; u++)
                    acc[u] += wo[768 + h + u] * Wf[(h + u) * 32 + lane];
            }
            float a4 = ((acc[0] + acc[1]) + (acc[2] + acc[3]))
                     + ((acc[4] + acc[5]) + (acc[6] + acc[7]));
            g_A4T[lane * D_ + d] = a4;               // transposed store
        } else {
            float a1x = 0, a1y = 0, a2x = 0, a2y = 0, a3x = 0, a3y = 0, bias = 0;
#pragma unroll
            for (int h = lane; h < H_; h += 32) {
                float w0 = wo[h];
                float w1 = wo[256 + h];
                float w2 = wo[512 + h];
                float w3 = wo[768 + h];
                a1x += w0 * Wp[h * 2 + 0];  a1y += w0 * Wp[h * 2 + 1];
                a2x += w1 * Wv[h * 2 + 0];  a2y += w1 * Wv[h * 2 + 1];
                a3x += w2 * Wa[h * 2 + 0];  a3y += w2 * Wa[h * 2 + 1];
                bias += w0 * bp[h] + w1 * bv[h] + w2 * ba[h] + w3 * bfr[h];
            }
#pragma unroll
            for (int off = 16; off > 0; off >>= 1) {
                a1x += __shfl_down_sync(0xffffffffu, a1x, off);
                a1y += __shfl_down_sync(0xffffffffu, a1y, off);
                a2x += __shfl_down_sync(0xffffffffu, a2x, off);
                a2y += __shfl_down_sync(0xffffffffu, a2y, off);
                a3x += __shfl_down_sync(0xffffffffu, a3x, off);
                a3y += __shfl_down_sync(0xffffffffu, a3y, off);
                bias += __shfl_down_sync(0xffffffffu, bias, off);
            }
            if (lane == 0) {
                g_a1x[d] = a1x; g_a1y[d] = a1y;
                g_a2x[d] = a2x; g_a2y[d] = a2y;
                g_a3x[d] = a3x; g_a3y[d] = a3y;
                g_cbias[d] = bias + bo[d];
            }
        }
    }
}

// ---------------------------------------------------------------------------
// 2) g[b,d] = cbias[d] + sum_j freq[b,j] * A4T[j][d].
//    grid (B_, 4) x 256 thr; thread = d within 256-chunk (coalesced A4T).
// ---------------------------------------------------------------------------
__global__ void __launch_bounds__(256) gtab_kernel() {
    int b = blockIdx.x;
    int d0 = blockIdx.y * 256;
    int tid = threadIdx.x;
    __shared__ float fr[32];
    if (tid < 32) {
        float re = 0.f, im = 0.f;
#pragma unroll
        for (int ch = 0; ch < DCHUNK; ch++) {
            float2 p = g_dpart[(b * 32 + tid) * DCHUNK + ch];
            re += p.x; im += p.y;
        }
        fr[tid] = sqrtf(re * re + im * im);
    }
    __syncthreads();

    int d = d0 + tid;
    float acc = g_cbias[d];
#pragma unroll
    for (int j = 0; j < 32; j++)
        acc += fr[j] * g_A4T[j * D_ + d];           // coalesced, fr broadcast
    g_g[b * D_ + d] = acc;
}

// ---------------------------------------------------------------------------
// 3) Main write kernel: HBM-write bound (537 MB of output), at the roofline.
//    PDL: stage the pattern tile first, then grid-dependency-sync, then pull
//    the precomputed coefficients.
// ---------------------------------------------------------------------------
__global__ void __launch_bounds__(256) main_kernel(const float* __restrict__ pattern,
                                                   float* __restrict__ out) {
    int b = blockIdx.y;
    int s0 = blockIdx.x * SCHUNK;
    int tid = threadIdx.x;
    int d = tid * 4;

    __shared__ float sp[(SCHUNK + 2) * 2];   // pattern[b, s0-2 .. s0+SCHUNK-1]
    if (tid < (SCHUNK + 2) * 2) {
        int s = s0 - 2 + (tid >> 1);
        int c = tid & 1;
        sp[tid] = (s >= 0) ? pattern[((size_t)b * S_ + s) * 2 + c] : 0.0f;
    }
#if __CUDA_ARCH__ >= 900
    cudaGridDependencySynchronize();
#endif
    float4 k1x = *(const float4*)(g_a1x + d);
    float4 k1y = *(const float4*)(g_a1y + d);
    float4 k2x = *(const float4*)(g_a2x + d);
    float4 k2y = *(const float4*)(g_a2y + d);
    float4 k3x = *(const float4*)(g_a3x + d);
    float4 k3y = *(const float4*)(g_a3y + d);
    float4 gg  = *(const float4*)(g_g + b * D_ + d);
    __syncthreads();

    float* op = out + ((size_t)b * S_ + s0) * D_ + d;

#pragma unroll
    for (int i = 0; i < SCHUNK; i++) {
        int s = s0 + i;
        float px = sp[(i + 2) * 2 + 0], py = sp[(i + 2) * 2 + 1];
        float mx = sp[(i + 1) * 2 + 0], my = sp[(i + 1) * 2 + 1];
        float nx = sp[(i + 0) * 2 + 0], ny = sp[(i + 0) * 2 + 1];

        float vx, vy, ax_, ay_;
        if (s == 0) {
            vx = 0.f; vy = 0.f; ax_ = 0.f; ay_ = 0.f;
        } else if (s == 1) {
            vx = px - mx; vy = py - my; ax_ = vx; ay_ = vy;
        } else {
            vx = px - mx; vy = py - my;
            ax_ = px - 2.f * mx + nx; ay_ = py - 2.f * my + ny;
        }

        float4 o;
        o.x = gg.x + k1x.x * px + k1y.x * py + k2x.x * vx + k2y.x * vy + k3x.x * ax_ + k3y.x * ay_;
        o.y = gg.y + k1x.y * px + k1y.y * py + k2x.y * vx + k2y.y * vy + k3x.y * ax_ + k3y.y * ay_;
        o.z = gg.z + k1x.z * px + k1y.z * py + k2x.z * vx + k2y.z * vy + k3x.z * ax_ + k3y.z * ay_;
        o.w = gg.w + k1x.w * px + k1y.w * py + k2x.w * vx + k2y.w * vy + k3x.w * ax_ + k3y.w * ay_;

        *(float4*)(op + (size_t)i * D_) = o;
    }
}

// ---------------------------------------------------------------------------
extern "C" void kernel_launch(void* const* d_in, const int* in_sizes, int n_in,
                              void* d_out, int out_size) {
    const float* pattern = (const float*)d_in[0];
    const float* Wp  = (const float*)d_in[1];
    const float* bp  = (const float*)d_in[2];
    const float* Wv  = (const float*)d_in[3];
    const float* bv  = (const float*)d_in[4];
    const float* Wa  = (const float*)d_in[5];
    const float* ba  = (const float*)d_in[6];
    const float* Wf  = (const float*)d_in[7];
    const float* bfr = (const float*)d_in[8];
    const float* Wo  = (const float*)d_in[9];
    const float* bo  = (const float*)d_in[10];
    float* out = (float*)d_out;

    pre_kernel<<<NDFT + NCOEFF, 1024>>>(pattern, Wp, bp, Wv, bv, Wa, ba,
                                        Wf, bfr, Wo, bo);
    gtab_kernel<<<dim3(B_, 4), 256>>>();

    // PDL on the final (dominant) kernel: overlap its launch/prologue with
    // gtab; main_kernel pre-syncs before touching precomputed tables.
    cudaLaunchAttribute at[1];
    at[0].id = cudaLaunchAttributeProgrammaticStreamSerialization;
    at[0].val.programmaticStreamSerializationAllowed = 1;

    cudaLaunchConfig_t cfg = {};
    cfg.gridDim = dim3(S_ / SCHUNK, B_);
    cfg.blockDim = dim3(256);
    cfg.stream = 0;
    cfg.attrs = at;
    cfg.numAttrs = 1;
    if (cudaLaunchKernelEx(&cfg, main_kernel, pattern, out) != cudaSuccess) {
        main_kernel<<<dim3(S_ / SCHUNK, B_), 256>>>(pattern, out);
    }
}